// round 3
// baseline (speedup 1.0000x reference)
#include <cuda_runtime.h>

// ---------------------------------------------------------------------------
// SpatialAttn2: B=16, L=32, N=256, P=16, H=4, F=12, HID=4, W=16
// out[B,W,F,N] | attn1[B,W,H,N,N] | attn2[B,W,N,N] | Wv1 | Wv2
// R3: poly-exp2 on FMA pipe (kills MUFU), fma.rn.f32x2 packed math,
//     4-row blocking layer1 (min crossbar traffic).
// ---------------------------------------------------------------------------

#define N_   256
#define P_   16
#define H_   4
#define F_   12
#define HID_ 4
#define W_   16
#define L_   32
#define BW_  256

static const unsigned long long OFF_A1  = 786432ull;
static const unsigned long long OFF_A2  = 786432ull + 67108864ull;
static const unsigned long long OFF_WV1 = 786432ull + 67108864ull + 16777216ull;
static const unsigned long long OFF_WV2 = OFF_WV1 + 256ull;
static const long long TOT_FULL = 84672960ll;

__device__ unsigned int g_maskbits[N_ * 8];

// ---------------------------------------------------------------------------
__global__ void pack_mask_kernel(const int* __restrict__ mask,
                                 const float* __restrict__ Wv1,
                                 const float* __restrict__ Wv2,
                                 float* __restrict__ out, int wW) {
    int t = blockIdx.x * 256 + threadIdx.x;
    int row  = t >> 3;
    int word = t & 7;
    const int* mr = mask + row * N_ + word * 32;
    unsigned int v = 0u;
#pragma unroll
    for (int b = 0; b < 32; b++) v |= (mr[b] > 0 ? (1u << b) : 0u);
    g_maskbits[t] = v;
    if (wW && blockIdx.x == 0) {
        out[OFF_WV1 + threadIdx.x] = Wv1[threadIdx.x];
        if (threadIdx.x < 192) out[OFF_WV2 + threadIdx.x] = Wv2[threadIdx.x];
    }
}

// ---------------------------------------------------------------------------
struct __align__(16) Smem {
    float xT [P_][N_];
    float h1T[P_][N_];
    float Qs [N_][20];
    float VT [F_][N_];
    unsigned int mb[N_][8];
    float Wa1[H_][P_][P_];
    float Wv1[H_][P_][HID_];
    float Wa2[P_][P_];
    float Wv2[P_][F_];
};

typedef unsigned long long u64;

__device__ __forceinline__ u64 pk2(float a, float b) {
    u64 r; asm("mov.b64 %0, {%1,%2};" : "=l"(r) : "f"(a), "f"(b)); return r;
}
__device__ __forceinline__ void upk2(u64 v, float& a, float& b) {
    asm("mov.b64 {%0,%1}, %2;" : "=f"(a), "=f"(b) : "l"(v));
}
__device__ __forceinline__ void upk2u(u64 v, unsigned& a, unsigned& b) {
    asm("mov.b64 {%0,%1}, %2;" : "=r"(a), "=r"(b) : "l"(v));
}
__device__ __forceinline__ u64 fma2_(u64 a, u64 b, u64 c) {
    u64 d; asm("fma.rn.f32x2 %0, %1, %2, %3;" : "=l"(d) : "l"(a), "l"(b), "l"(c)); return d;
}
__device__ __forceinline__ u64 add2_(u64 a, u64 b) {
    u64 d; asm("add.rn.f32x2 %0, %1, %2;" : "=l"(d) : "l"(a), "l"(b)); return d;
}

__device__ __forceinline__ float warp_max(float v) {
#pragma unroll
    for (int o = 16; o > 0; o >>= 1) v = fmaxf(v, __shfl_xor_sync(0xffffffffu, v, o));
    return v;
}
__device__ __forceinline__ float warp_sum(float v) {
#pragma unroll
    for (int o = 16; o > 0; o >>= 1) v += __shfl_xor_sync(0xffffffffu, v, o);
    return v;
}

// packed exp2-based exp(s - m): inputs packed scores s2, mm2 = pack(-m*log2e).
// Per pair: t=s*log2e-m*log2e; n=rint(t) via magic; 2^f poly deg-4; splice 2^n.
#define EXP_PAIR(s2v, elo, ehi)                                                 \
    {                                                                           \
        u64 t2  = fma2_((s2v), kL2E, mm2);                                      \
        u64 bg2 = add2_(t2, kMAG);                                              \
        u64 nf2 = add2_(bg2, kMAGN);                                            \
        u64 f2  = fma2_(nf2, kNEG1, t2);                                        \
        u64 p2  = fma2_(kC4, f2, kC3);                                          \
        p2 = fma2_(p2, f2, kC2);                                                \
        p2 = fma2_(p2, f2, kC1);                                                \
        p2 = fma2_(p2, f2, kONE);                                               \
        unsigned blo_, bhi_; upk2u(bg2, blo_, bhi_);                            \
        float plo_, phi_;    upk2(p2, plo_, phi_);                              \
        elo = __int_as_float(__float_as_int(plo_) + (int)(blo_ << 23));         \
        ehi = __int_as_float(__float_as_int(phi_) + (int)(bhi_ << 23));         \
    }

__global__ void __launch_bounds__(256, 1)
spatial_attn_kernel(const float* __restrict__ inp,
                    const float* __restrict__ Wa1,
                    const float* __restrict__ Wv1,
                    const float* __restrict__ Wa2,
                    const float* __restrict__ Wv2,
                    float* __restrict__ out, int wA) {
    extern __shared__ char smraw[];
    Smem& S = *reinterpret_cast<Smem*>(smraw);
    const int tid  = threadIdx.x;
    const int lane = tid & 31;
    const int wid  = tid >> 5;
    const int bw   = blockIdx.x;
    const int b    = bw >> 4;
    const int w    = bw & 15;

    // packed constants for the exp path
    const u64 kL2E  = pk2(1.44269504089f, 1.44269504089f);
    const u64 kMAG  = pk2(12582912.f, 12582912.f);     // 1.5 * 2^23
    const u64 kMAGN = pk2(-12582912.f, -12582912.f);
    const u64 kNEG1 = pk2(-1.f, -1.f);
    const u64 kC4   = pk2(9.61812911e-3f, 9.61812911e-3f);
    const u64 kC3   = pk2(5.55041087e-2f, 5.55041087e-2f);
    const u64 kC2   = pk2(2.40226507e-1f, 2.40226507e-1f);
    const u64 kC1   = pk2(6.93147181e-1f, 6.93147181e-1f);
    const u64 kONE  = pk2(1.f, 1.f);

    // ---- stage 0: load xT, mask bits, weights ------------------------------
#pragma unroll
    for (int p = 0; p < P_; p++)
        S.xT[p][tid] = inp[(b * L_ + w + p) * N_ + tid];
#pragma unroll
    for (int k = 0; k < 8; k++)
        (&S.mb[0][0])[tid + 256 * k] = g_maskbits[tid + 256 * k];
#pragma unroll
    for (int k = 0; k < 4; k++)
        (&S.Wa1[0][0][0])[tid + 256 * k] = Wa1[tid + 256 * k];
    (&S.Wv1[0][0][0])[tid] = Wv1[tid];
    (&S.Wa2[0][0])[tid]    = Wa2[tid];
    if (tid < 192) (&S.Wv2[0][0])[tid] = Wv2[tid];
    __syncthreads();

    float* a1 = out + OFF_A1 + (unsigned long long)bw * (H_ * N_ * N_);
    float* a2 = out + OFF_A2 + (unsigned long long)bw * (N_ * N_);

    // =========================== layer 1 (4 heads) ===========================
#pragma unroll 1
    for (int h = 0; h < H_; h++) {
        // stage 1: Q = 0.25 * X @ Wa1[h] ; VT = (X @ Wv1[h])^T
        {
            float q[P_], v[HID_];
#pragma unroll
            for (int j = 0; j < P_; j++) q[j] = 0.f;
#pragma unroll
            for (int o = 0; o < HID_; o++) v[o] = 0.f;
#pragma unroll
            for (int i = 0; i < P_; i++) {
                float xi = S.xT[i][tid];
#pragma unroll
                for (int j = 0; j < P_; j++) q[j] += xi * S.Wa1[h][i][j];
#pragma unroll
                for (int o = 0; o < HID_; o++) v[o] += xi * S.Wv1[h][i][o];
            }
#pragma unroll
            for (int j4 = 0; j4 < 4; j4++) {
                float4 t4 = make_float4(q[j4*4+0]*0.25f, q[j4*4+1]*0.25f,
                                        q[j4*4+2]*0.25f, q[j4*4+3]*0.25f);
                *reinterpret_cast<float4*>(&S.Qs[tid][j4*4]) = t4;
            }
#pragma unroll
            for (int o = 0; o < HID_; o++) S.VT[o][tid] = v[o];
        }
        __syncthreads();

        float* a1h = a1 + h * N_ * N_;
        // stage 2: 4 rows per pass, lane owns cols {lane*4, 128+lane*4}
#pragma unroll 1
        for (int rg = 0; rg < 8; rg++) {
            const int row0 = (wid << 5) + (rg << 2);
            float q[4][P_];
#pragma unroll
            for (int r = 0; r < 4; r++)
#pragma unroll
                for (int j4 = 0; j4 < 4; j4++) {
                    float4 t4 = *reinterpret_cast<const float4*>(&S.Qs[row0 + r][j4*4]);
                    q[r][j4*4+0] = t4.x; q[r][j4*4+1] = t4.y;
                    q[r][j4*4+2] = t4.z; q[r][j4*4+3] = t4.w;
                }
            // packed score accumulators: [c][r][pair]
            u64 s2[2][4][2];
#pragma unroll
            for (int c = 0; c < 2; c++)
#pragma unroll
                for (int r = 0; r < 4; r++) {
                    s2[c][r][0] = pk2(0.f, 0.f);
                    s2[c][r][1] = pk2(0.f, 0.f);
                }
#pragma unroll
            for (int i = 0; i < P_; i++) {
                u64 qq[4];
#pragma unroll
                for (int r = 0; r < 4; r++) qq[r] = pk2(q[r][i], q[r][i]);
#pragma unroll
                for (int c = 0; c < 2; c++) {
                    ulonglong2 xv = *reinterpret_cast<const ulonglong2*>(
                        &S.xT[i][c * 128 + (lane << 2)]);
#pragma unroll
                    for (int r = 0; r < 4; r++) {
                        s2[c][r][0] = fma2_(qq[r], xv.x, s2[c][r][0]);
                        s2[c][r][1] = fma2_(qq[r], xv.y, s2[c][r][1]);
                    }
                }
            }
            // mask bits, rowmax, exp, sum
            unsigned bb[4];
            float e[4][8];
            float inv[4];
#pragma unroll
            for (int r = 0; r < 4; r++) {
                unsigned sh  = (lane & 7) << 2;
                unsigned mw0 = S.mb[row0 + r][(lane >> 3)];
                unsigned mw1 = S.mb[row0 + r][4 + (lane >> 3)];
                bb[r] = ((mw0 >> sh) & 0xFu) | (((mw1 >> sh) & 0xFu) << 4);
                float mx = -1e30f;
#pragma unroll
                for (int c = 0; c < 2; c++)
#pragma unroll
                    for (int pr = 0; pr < 2; pr++) {
                        float a_, b_; upk2(s2[c][r][pr], a_, b_);
                        int k = c * 4 + pr * 2;
                        mx = fmaxf(mx, ((bb[r] >> k) & 1u) ? a_ : -1e30f);
                        mx = fmaxf(mx, ((bb[r] >> (k + 1)) & 1u) ? b_ : -1e30f);
                    }
                float m_  = warp_max(mx);
                float mng = -m_ * 1.44269504089f;
                u64 mm2   = pk2(mng, mng);
                float sm  = 0.f;
#pragma unroll
                for (int c = 0; c < 2; c++)
#pragma unroll
                    for (int pr = 0; pr < 2; pr++) {
                        int k = c * 4 + pr * 2;
                        float elo, ehi;
                        EXP_PAIR(s2[c][r][pr], elo, ehi);
                        elo = ((bb[r] >> k) & 1u) ? elo : 0.f;
                        ehi = ((bb[r] >> (k + 1)) & 1u) ? ehi : 0.f;
                        e[r][k] = elo; e[r][k + 1] = ehi;
                        sm += elo + ehi;
                    }
                sm = warp_sum(sm);
                inv[r] = __frcp_rn(sm);
            }
            // normalize, write attn, aggregate h1 (packed)
            u64 acc2[4][HID_];
#pragma unroll
            for (int r = 0; r < 4; r++)
#pragma unroll
                for (int o = 0; o < HID_; o++) acc2[r][o] = pk2(0.f, 0.f);
#pragma unroll
            for (int c = 0; c < 2; c++) {
                const int m0 = c * 128 + (lane << 2);
                u64 ea[4], eb[4];
#pragma unroll
                for (int r = 0; r < 4; r++) {
                    float n0 = e[r][c*4+0] * inv[r];
                    float n1 = e[r][c*4+1] * inv[r];
                    float n2 = e[r][c*4+2] * inv[r];
                    float n3 = e[r][c*4+3] * inv[r];
                    if (wA) {
                        float4 w4 = make_float4(n0, n1, n2, n3);
                        __stcs(reinterpret_cast<float4*>(&a1h[(row0 + r) * N_ + m0]), w4);
                    }
                    ea[r] = pk2(n0, n1);
                    eb[r] = pk2(n2, n3);
                }
#pragma unroll
                for (int o = 0; o < HID_; o++) {
                    ulonglong2 vv = *reinterpret_cast<const ulonglong2*>(&S.VT[o][m0]);
#pragma unroll
                    for (int r = 0; r < 4; r++) {
                        acc2[r][o] = fma2_(ea[r], vv.x, acc2[r][o]);
                        acc2[r][o] = fma2_(eb[r], vv.y, acc2[r][o]);
                    }
                }
            }
#pragma unroll
            for (int r = 0; r < 4; r++) {
                float hv[HID_];
#pragma unroll
                for (int o = 0; o < HID_; o++) {
                    float a_, b_; upk2(acc2[r][o], a_, b_);
                    hv[o] = warp_sum(a_ + b_);
                }
                if (lane == 0) {
#pragma unroll
                    for (int o = 0; o < HID_; o++)
                        S.h1T[h * HID_ + o][row0 + r] = hv[o];
                }
            }
        }
        __syncthreads();
    }

    // ================================ layer 2 ================================
    {
        float q[P_], v[F_];
#pragma unroll
        for (int j = 0; j < P_; j++) q[j] = 0.f;
#pragma unroll
        for (int o = 0; o < F_; o++) v[o] = 0.f;
#pragma unroll
        for (int i = 0; i < P_; i++) {
            float xi = S.h1T[i][tid];
#pragma unroll
            for (int j = 0; j < P_; j++) q[j] += xi * S.Wa2[i][j];
#pragma unroll
            for (int o = 0; o < F_; o++) v[o] += xi * S.Wv2[i][o];
        }
#pragma unroll
        for (int j4 = 0; j4 < 4; j4++) {
            float4 t4 = make_float4(q[j4*4+0]*0.25f, q[j4*4+1]*0.25f,
                                    q[j4*4+2]*0.25f, q[j4*4+3]*0.25f);
            *reinterpret_cast<float4*>(&S.Qs[tid][j4*4]) = t4;
        }
#pragma unroll
        for (int o = 0; o < F_; o++) S.VT[o][tid] = v[o];
    }
    __syncthreads();

#pragma unroll 1
    for (int rg = 0; rg < 16; rg++) {
        const int row0 = (wid << 5) + (rg << 1);
        float q[2][P_];
#pragma unroll
        for (int r = 0; r < 2; r++)
#pragma unroll
            for (int j4 = 0; j4 < 4; j4++) {
                float4 t4 = *reinterpret_cast<const float4*>(&S.Qs[row0 + r][j4*4]);
                q[r][j4*4+0] = t4.x; q[r][j4*4+1] = t4.y;
                q[r][j4*4+2] = t4.z; q[r][j4*4+3] = t4.w;
            }
        u64 s2[2][2][2];
#pragma unroll
        for (int c = 0; c < 2; c++)
#pragma unroll
            for (int r = 0; r < 2; r++) {
                s2[c][r][0] = pk2(0.f, 0.f);
                s2[c][r][1] = pk2(0.f, 0.f);
            }
#pragma unroll
        for (int i = 0; i < P_; i++) {
            u64 qq[2];
#pragma unroll
            for (int r = 0; r < 2; r++) qq[r] = pk2(q[r][i], q[r][i]);
#pragma unroll
            for (int c = 0; c < 2; c++) {
                ulonglong2 xv = *reinterpret_cast<const ulonglong2*>(
                    &S.h1T[i][c * 128 + (lane << 2)]);
#pragma unroll
                for (int r = 0; r < 2; r++) {
                    s2[c][r][0] = fma2_(qq[r], xv.x, s2[c][r][0]);
                    s2[c][r][1] = fma2_(qq[r], xv.y, s2[c][r][1]);
                }
            }
        }
        unsigned bb[2];
        float e[2][8];
        float inv[2];
#pragma unroll
        for (int r = 0; r < 2; r++) {
            unsigned sh  = (lane & 7) << 2;
            unsigned mw0 = S.mb[row0 + r][(lane >> 3)];
            unsigned mw1 = S.mb[row0 + r][4 + (lane >> 3)];
            bb[r] = ((mw0 >> sh) & 0xFu) | (((mw1 >> sh) & 0xFu) << 4);
            float mx = -1e30f;
#pragma unroll
            for (int c = 0; c < 2; c++)
#pragma unroll
                for (int pr = 0; pr < 2; pr++) {
                    float a_, b_; upk2(s2[c][r][pr], a_, b_);
                    int k = c * 4 + pr * 2;
                    mx = fmaxf(mx, ((bb[r] >> k) & 1u) ? a_ : -1e30f);
                    mx = fmaxf(mx, ((bb[r] >> (k + 1)) & 1u) ? b_ : -1e30f);
                }
            float m_  = warp_max(mx);
            float mng = -m_ * 1.44269504089f;
            u64 mm2   = pk2(mng, mng);
            float sm  = 0.f;
#pragma unroll
            for (int c = 0; c < 2; c++)
#pragma unroll
                for (int pr = 0; pr < 2; pr++) {
                    int k = c * 4 + pr * 2;
                    float elo, ehi;
                    EXP_PAIR(s2[c][r][pr], elo, ehi);
                    elo = ((bb[r] >> k) & 1u) ? elo : 0.f;
                    ehi = ((bb[r] >> (k + 1)) & 1u) ? ehi : 0.f;
                    e[r][k] = elo; e[r][k + 1] = ehi;
                    sm += elo + ehi;
                }
            sm = warp_sum(sm);
            inv[r] = __frcp_rn(sm);
        }
        u64 acc2[2][F_];
#pragma unroll
        for (int r = 0; r < 2; r++)
#pragma unroll
            for (int o = 0; o < F_; o++) acc2[r][o] = pk2(0.f, 0.f);
#pragma unroll
        for (int c = 0; c < 2; c++) {
            const int m0 = c * 128 + (lane << 2);
            u64 ea[2], eb[2];
#pragma unroll
            for (int r = 0; r < 2; r++) {
                float n0 = e[r][c*4+0] * inv[r];
                float n1 = e[r][c*4+1] * inv[r];
                float n2 = e[r][c*4+2] * inv[r];
                float n3 = e[r][c*4+3] * inv[r];
                if (wA) {
                    float4 w4 = make_float4(n0, n1, n2, n3);
                    __stcs(reinterpret_cast<float4*>(&a2[(row0 + r) * N_ + m0]), w4);
                }
                ea[r] = pk2(n0, n1);
                eb[r] = pk2(n2, n3);
            }
#pragma unroll
            for (int o = 0; o < F_; o++) {
                ulonglong2 vv = *reinterpret_cast<const ulonglong2*>(&S.VT[o][m0]);
#pragma unroll
                for (int r = 0; r < 2; r++) {
                    acc2[r][o] = fma2_(ea[r], vv.x, acc2[r][o]);
                    acc2[r][o] = fma2_(eb[r], vv.y, acc2[r][o]);
                }
            }
        }
#pragma unroll
        for (int r = 0; r < 2; r++) {
            float hv[F_];
#pragma unroll
            for (int o = 0; o < F_; o++) {
                float a_, b_; upk2(acc2[r][o], a_, b_);
                hv[o] = warp_sum(a_ + b_);
            }
            if (lane == 0) {
#pragma unroll
                for (int f = 0; f < F_; f++)
                    out[((unsigned long long)bw * F_ + f) * N_ + row0 + r] = hv[f];
            }
        }
    }
}

// ---------------------------------------------------------------------------
extern "C" void kernel_launch(void* const* d_in, const int* in_sizes, int n_in,
                              void* d_out, int out_size) {
    const float* inp  = (const float*)d_in[0];
    const int*   mask = (const int*)  d_in[1];
    const float* Wa1  = (const float*)d_in[2];
    const float* Wv1  = (const float*)d_in[3];
    const float* Wa2  = (const float*)d_in[4];
    const float* Wv2  = (const float*)d_in[5];
    float* out = (float*)d_out;

    const int wA = (out_size >= (int)(OFF_A2 + (unsigned long long)BW_ * N_ * N_)) ? 1 : 0;
    const int wW = (out_size >= (int)TOT_FULL) ? 1 : 0;

    cudaFuncSetAttribute(spatial_attn_kernel,
                         cudaFuncAttributeMaxDynamicSharedMemorySize,
                         (int)sizeof(Smem));

    pack_mask_kernel<<<8, 256>>>(mask, Wv1, Wv2, out, wW);
    spatial_attn_kernel<<<BW_, 256, sizeof(Smem)>>>(inp, Wa1, Wv1, Wa2, Wv2, out, wA);
}